// round 2
// baseline (speedup 1.0000x reference)
#include <cuda_runtime.h>
#include <math.h>

#define BATCH   4
#define SEQ     1024
#define DMODEL  1024
#define NH      16
#define HD      64
#define BHTOT   (BATCH*NH)

// ---- scratch (device globals; no allocation allowed) ----
__device__ float g_q [BATCH*NH*SEQ*HD];
__device__ float g_k [BATCH*NH*SEQ*HD];
__device__ float g_v [BATCH*NH*SEQ*HD];
__device__ float g_ao[BATCH*SEQ*DMODEL];

// ============================================================
// GEMM: C[m,e] = sum_d A[m,d] * W[e,d]   (both K-major / NT)
// MODE 0: A := g_ao (device global, resolved in DEVICE code),
//         write Cout[m*DMODEL + e]
// MODE 1: A := x (harness pointer), z-dim selects Wq/Wk/Wv,
//         scatter into (B,H,N,hd) q/k/v device globals
// BM=BN=128, BK=16, 256 threads, 8x8 microtile
// ============================================================
template<int MODE>
__global__ __launch_bounds__(256) void gemm_nt_kernel(
    const float* __restrict__ Ain,
    const float* __restrict__ W0,
    const float* __restrict__ W1,
    const float* __restrict__ W2,
    float* __restrict__ Cout)
{
    __shared__ float As[16][132];   // transposed: As[k][m], pad for STS conflicts
    __shared__ float Bs[16][132];

    const int K = DMODEL;
    const float* A;
    const float* W;
    float* qkv_dst = nullptr;
    if (MODE == 1) {
        int z = blockIdx.z;
        A       = Ain;
        W       = (z == 0) ? W0  : (z == 1) ? W1  : W2;
        qkv_dst = (z == 0) ? g_q : (z == 1) ? g_k : g_v;
    } else {
        A = g_ao;       // device-side resolution of the device global
        W = W0;
    }

    const int tid = threadIdx.x;
    const int tx = tid & 15;
    const int ty = tid >> 4;
    const int row0 = blockIdx.y * 128;
    const int col0 = blockIdx.x * 128;

    float acc[8][8];
#pragma unroll
    for (int i = 0; i < 8; i++)
#pragma unroll
        for (int j = 0; j < 8; j++) acc[i][j] = 0.0f;

    for (int kt = 0; kt < K; kt += 16) {
#pragma unroll
        for (int s = 0; s < 2; s++) {
            int seg = tid + s * 256;         // 0..511
            int r   = seg >> 2;              // 0..127
            int c   = (seg & 3) << 2;        // 0,4,8,12
            float4 av = *(const float4*)(A + (size_t)(row0 + r) * K + kt + c);
            As[c+0][r] = av.x; As[c+1][r] = av.y; As[c+2][r] = av.z; As[c+3][r] = av.w;
            float4 bv = *(const float4*)(W + (size_t)(col0 + r) * K + kt + c);
            Bs[c+0][r] = bv.x; Bs[c+1][r] = bv.y; Bs[c+2][r] = bv.z; Bs[c+3][r] = bv.w;
        }
        __syncthreads();
#pragma unroll
        for (int k = 0; k < 16; k++) {
            float a[8], b[8];
            *(float4*)&a[0] = *(const float4*)&As[k][ty*4];
            *(float4*)&a[4] = *(const float4*)&As[k][64 + ty*4];
            *(float4*)&b[0] = *(const float4*)&Bs[k][tx*4];
            *(float4*)&b[4] = *(const float4*)&Bs[k][64 + tx*4];
#pragma unroll
            for (int i = 0; i < 8; i++)
#pragma unroll
                for (int j = 0; j < 8; j++)
                    acc[i][j] += a[i] * b[j];
        }
        __syncthreads();
    }

#pragma unroll
    for (int i = 0; i < 8; i++) {
        int m = row0 + ((i < 4) ? (ty*4 + i) : (64 + ty*4 + i - 4));
#pragma unroll
        for (int j = 0; j < 8; j++) {
            int e = col0 + ((j < 4) ? (tx*4 + j) : (64 + tx*4 + j - 4));
            if (MODE == 1) {
                int b_ = m >> 10;          // m / SEQ
                int n_ = m & 1023;
                int h_ = e >> 6;           // e / HD
                int d_ = e & 63;
                qkv_dst[(((size_t)b_ * NH + h_) * SEQ + n_) * HD + d_] = acc[i][j];
            } else {
                Cout[(size_t)m * DMODEL + e] = acc[i][j];
            }
        }
    }
}

// ============================================================
// 2D axial RoPE + RMSNorm, in place on g_q / g_k.
// One warp per (b,h,n) row of 64. Lane L owns the pair (2L, 2L+1),
// which is exactly one rotation pair of the axial RoPE.
// ============================================================
__global__ __launch_bounds__(128) void rope_norm_kernel(
    const int* __restrict__ ridx,
    const float* __restrict__ qw,
    const float* __restrict__ kw)
{
    int warp = threadIdx.x >> 5;
    int lane = threadIdx.x & 31;
    size_t row = (size_t)blockIdx.x * 4 + warp;       // 0 .. BHTOT*SEQ-1
    float* base = ((blockIdx.y == 0) ? g_q : g_k) + row * HD;
    const float* w = (blockIdx.y == 0) ? qw : kw;

    int n   = (int)(row & (SEQ - 1));                 // row = bh*SEQ + n
    int idx = ridx[n];

    float a = base[lane*2 + 0];
    float b = base[lane*2 + 1];

    if (idx >= 0) {
        // pos_y = idx / GRID, pos_x = idx % GRID  (GRID=32)
        float pos = (lane < 16) ? (float)(idx >> 5) : (float)(idx & 31);
        int   jj  = lane & 15;
        // inv_freq = 10000^(-jj/16) ;  ln(10000)/16 = 0.575646273248511...
        float invf = expf(-0.5756462732485115f * (float)jj);
        float ang  = pos * invf;
        float s, c;
        sincosf(ang, &s, &c);
        float na = a * c - b * s;     // x*cos + rotate_half(x)*sin, pairwise
        float nb = b * c + a * s;
        a = na; b = nb;
    }

    // RMSNorm over the 64-dim head
    float ss = a * a + b * b;
#pragma unroll
    for (int m = 16; m >= 1; m >>= 1)
        ss += __shfl_xor_sync(0xffffffffu, ss, m);
    float rinv = rsqrtf(ss * (1.0f / 64.0f) + 1e-6f);

    base[lane*2 + 0] = a * rinv * w[lane*2 + 0];
    base[lane*2 + 1] = b * rinv * w[lane*2 + 1];
}

// ============================================================
// Attention: per CTA = one 64-query block of one (b,h).
// Soft-cap bounds scores to |s|<=8 (rmsnormed q,k) -> no max
// tracking needed; single-pass sum + accumulate.
// tanh via odd polynomial (|s/50| <= 0.162, err ~1e-9).
// ============================================================
__global__ __launch_bounds__(256) void attn_kernel()
{
    __shared__ float Qs[64][64];    // transposed: Qs[d][q]
    __shared__ float KPs[64][64];   // Ks_t[d][k]  -> later Ps_t[k][q]
    __shared__ float Vs[64][64];    // natural:   Vs[k][d]

    const int tid = threadIdx.x;
    const int tx = tid & 15;
    const int ty = tid >> 4;
    const int bh = blockIdx.y;                 // 0..63
    const int qb = blockIdx.x;                 // 0..15

    const float* qbase = g_q + ((size_t)bh * SEQ + qb * 64) * HD;
    const float* kbase = g_k + (size_t)bh * SEQ * HD;
    const float* vbase = g_v + (size_t)bh * SEQ * HD;

    // load Q tile transposed
    {
        int r = tid >> 2;            // 0..63
        int c = (tid & 3) << 2;      // 0,4,8,12
        const float* src = qbase + (size_t)r * HD + c;
#pragma unroll
        for (int rep = 0; rep < 4; rep++) {   // cover all 64 d per row
            float4 qv = *(const float4*)(src + rep * 16);
            int cc = c + rep * 16;
            Qs[cc+0][r] = qv.x; Qs[cc+1][r] = qv.y; Qs[cc+2][r] = qv.z; Qs[cc+3][r] = qv.w;
        }
    }

    float o[4][4];
    float lsum[4];
#pragma unroll
    for (int i = 0; i < 4; i++) {
        lsum[i] = 0.0f;
#pragma unroll
        for (int j = 0; j < 4; j++) o[i][j] = 0.0f;
    }

    const float scale = 0.125f;                // hd^-0.5
    const float icap  = 1.0f / 50.0f;

    for (int t = 0; t < 16; t++) {
        __syncthreads();   // protect KPs/Vs from previous iter readers (and Q store on t=0)
        // load K tile (transposed) and V tile (natural)
        {
            int r = tid >> 2;
            int c = (tid & 3) << 2;
            const float* ksrc = kbase + ((size_t)t * 64 + r) * HD + c;
            const float* vsrc = vbase + ((size_t)t * 64 + r) * HD + c;
#pragma unroll
            for (int rep = 0; rep < 4; rep++) {
                float4 kv = *(const float4*)(ksrc + rep * 16);
                int cc = c + rep * 16;
                KPs[cc+0][r] = kv.x; KPs[cc+1][r] = kv.y; KPs[cc+2][r] = kv.z; KPs[cc+3][r] = kv.w;
                float4 vv = *(const float4*)(vsrc + rep * 16);
                *(float4*)&Vs[r][cc] = vv;
            }
        }
        __syncthreads();

        // S = Q K^T  (4x4 microtile per thread)
        float s[4][4];
#pragma unroll
        for (int i = 0; i < 4; i++)
#pragma unroll
            for (int j = 0; j < 4; j++) s[i][j] = 0.0f;

#pragma unroll 16
        for (int d = 0; d < 64; d++) {
            float a[4], b[4];
            *(float4*)a = *(const float4*)&Qs[d][ty*4];
            *(float4*)b = *(const float4*)&KPs[d][tx*4];
#pragma unroll
            for (int i = 0; i < 4; i++)
#pragma unroll
                for (int j = 0; j < 4; j++)
                    s[i][j] += a[i] * b[j];
        }

        // softcap (poly tanh) + exp; accumulate row partial sums
#pragma unroll
        for (int i = 0; i < 4; i++) {
#pragma unroll
            for (int j = 0; j < 4; j++) {
                float sv = s[i][j] * scale;
                float u  = sv * icap;
                float u2 = u * u;
                // 50*tanh(sv/50) = sv*(1 - u2/3 + 2u2^2/15 - 17u2^3/315)
                float capped = sv * (1.0f + u2 * (-0.333333333f +
                               u2 * (0.1333333333f + u2 * (-0.05396825397f))));
                float p = __expf(capped);
                lsum[i] += p;
                s[i][j] = p;
            }
        }

        __syncthreads();   // all reads of KPs (K) done before rewriting with P
        // store P transposed: Ps_t[k][q]
#pragma unroll
        for (int i = 0; i < 4; i++)
#pragma unroll
            for (int j = 0; j < 4; j++)
                KPs[tx*4 + j][ty*4 + i] = s[i][j];
        __syncthreads();

        // O += P V   (inner dim = k)
#pragma unroll 16
        for (int kk = 0; kk < 64; kk++) {
            float p[4], v[4];
            *(float4*)p = *(const float4*)&KPs[kk][ty*4];
            *(float4*)v = *(const float4*)&Vs[kk][tx*4];
#pragma unroll
            for (int i = 0; i < 4; i++)
#pragma unroll
                for (int j = 0; j < 4; j++)
                    o[i][j] += p[i] * v[j];
        }
    }

    // reduce lsum across the 16 tx-threads of each row; normalize; write
    const int b_ = bh >> 4;
    const int h_ = bh & 15;
#pragma unroll
    for (int i = 0; i < 4; i++) {
        float l = lsum[i];
        l += __shfl_xor_sync(0xffffffffu, l, 8);
        l += __shfl_xor_sync(0xffffffffu, l, 4);
        l += __shfl_xor_sync(0xffffffffu, l, 2);
        l += __shfl_xor_sync(0xffffffffu, l, 1);
        float inv = 1.0f / l;
        int n = qb * 64 + ty * 4 + i;
        float* dst = g_ao + ((size_t)b_ * SEQ + n) * DMODEL + h_ * HD + tx * 4;
        float4 r;
        r.x = o[i][0] * inv; r.y = o[i][1] * inv;
        r.z = o[i][2] * inv; r.w = o[i][3] * inv;
        *(float4*)dst = r;
    }
}

// ============================================================
// launcher
// ============================================================
extern "C" void kernel_launch(void* const* d_in, const int* in_sizes, int n_in,
                              void* d_out, int out_size)
{
    const float* x   = (const float*)d_in[0];
    const float* Wq  = (const float*)d_in[1];
    const float* Wk  = (const float*)d_in[2];
    const float* Wv  = (const float*)d_in[3];
    const float* Wo  = (const float*)d_in[4];
    const float* qw  = (const float*)d_in[5];
    const float* kw  = (const float*)d_in[6];
    const int*   ri  = (const int*)  d_in[7];
    float* out = (float*)d_out;

    // 1) QKV projections -> g_q/g_k/g_v in (B,H,N,hd)
    gemm_nt_kernel<1><<<dim3(DMODEL/128, (BATCH*SEQ)/128, 3), 256>>>(x, Wq, Wk, Wv, nullptr);

    // 2) RoPE + RMSNorm in place on q and k
    rope_norm_kernel<<<dim3((BHTOT*SEQ)/4, 2), 128>>>(ri, qw, kw);

    // 3) attention -> g_ao in (B,N,D)
    attn_kernel<<<dim3(SEQ/64, BHTOT), 256>>>();

    // 4) output projection -> d_out (A resolved device-side to g_ao)
    gemm_nt_kernel<0><<<dim3(DMODEL/128, (BATCH*SEQ)/128, 1), 256>>>(nullptr, Wo, nullptr, nullptr, out);
}

// round 13
// speedup vs baseline: 1.8411x; 1.8411x over previous
#include <cuda_runtime.h>
#include <cuda_fp16.h>
#include <math.h>
#include <stdint.h>

#define BATCH   4
#define SEQ     1024
#define DMODEL  1024
#define NH      16
#define HD      64
#define BHTOT   (BATCH*NH)

// ---- scratch (device globals; no allocation allowed) ----
__device__ float  g_q  [BATCH*NH*SEQ*HD];
__device__ float  g_k  [BATCH*NH*SEQ*HD];
__device__ float  g_v  [BATCH*NH*SEQ*HD];
__device__ __half g_xh [BATCH*SEQ*DMODEL];
__device__ __half g_wh [4*DMODEL*DMODEL];     // Wq,Wk,Wv,Wo in fp16
__device__ __half g_aoh[BATCH*SEQ*DMODEL];    // attention output (fp16)

// ============================================================
// PTX helpers (baseline sm_80+ features only — NO tcgen05)
// ============================================================
__device__ __forceinline__ uint32_t smem_u32(const void* p) {
    uint32_t a;
    asm("{ .reg .u64 t; cvta.to.shared.u64 t, %1; cvt.u32.u64 %0, t; }"
        : "=r"(a) : "l"(p));
    return a;
}

#define CP16(dst, src) \
    asm volatile("cp.async.cg.shared.global [%0], [%1], 16;" \
        :: "r"(dst), "l"(src) : "memory")
#define CP_COMMIT() asm volatile("cp.async.commit_group;" ::: "memory")
#define CP_WAIT(n)  asm volatile("cp.async.wait_group %0;" :: "n"(n) : "memory")

#define LDSM4(r, addr) \
    asm volatile("ldmatrix.sync.aligned.m8n8.x4.shared.b16 {%0,%1,%2,%3}, [%4];" \
        : "=r"((r)[0]), "=r"((r)[1]), "=r"((r)[2]), "=r"((r)[3]) : "r"(addr))

#define MMA16816(c, a, b) \
    asm volatile("mma.sync.aligned.m16n8k16.row.col.f32.f16.f16.f32 " \
        "{%0,%1,%2,%3}, {%4,%5,%6,%7}, {%8,%9}, {%0,%1,%2,%3};" \
        : "+f"((c)[0]), "+f"((c)[1]), "+f"((c)[2]), "+f"((c)[3]) \
        : "r"((a)[0]), "r"((a)[1]), "r"((a)[2]), "r"((a)[3]), \
          "r"((b)[0]), "r"((b)[1]))

// smem swizzle: 64B rows (32 fp16), 4 chunks of 16B; chunk ^= (row>>1)&3
__device__ __forceinline__ uint32_t swz(int row, int chunk) {
    return (uint32_t)(row * 64 + ((chunk ^ ((row >> 1) & 3)) << 4));
}

// ============================================================
// fp32 -> fp16 conversion of x and the four weight matrices.
// ============================================================
__global__ __launch_bounds__(256) void convert_kernel(
    const float* __restrict__ x,
    const float* __restrict__ wq, const float* __restrict__ wk,
    const float* __restrict__ wv, const float* __restrict__ wo)
{
    int v = blockIdx.x * 256 + threadIdx.x;            // 0 .. 2M-1
    const int XV = (BATCH * SEQ * DMODEL) / 4;         // 1M float4
    const int WV = (DMODEL * DMODEL) / 4;              // 256K float4
    const float* src;
    __half* dst;
    if (v < XV) {
        src = x + (size_t)v * 4;
        dst = g_xh + (size_t)v * 4;
    } else {
        int w  = v - XV;
        int wi = w / WV;
        int off = w - wi * WV;
        const float* ws = (wi == 0) ? wq : (wi == 1) ? wk : (wi == 2) ? wv : wo;
        src = ws + (size_t)off * 4;
        dst = g_wh + (size_t)wi * DMODEL * DMODEL + (size_t)off * 4;
    }
    float4 f = *(const float4*)src;
    __half2 h0 = __floats2half2_rn(f.x, f.y);
    __half2 h1 = __floats2half2_rn(f.z, f.w);
    *(__half2*)(dst)     = h0;
    *(__half2*)(dst + 2) = h1;
}

// ============================================================
// fp16 mma.sync GEMM:  C[m,e] = sum_d A[m,d] * W[e,d]   (NT)
// BM=BN=128, BK=32, 256 threads (8 warps as 2x4, 64x32 per warp).
// 3-stage cp.async pipeline, ldmatrix fragments (B non-trans:
// smem row=n contiguous-k IS col-major K x N — fragment matches).
// ============================================================
template<int MODE>
__global__ __launch_bounds__(256) void gemm_hmma_kernel(float* __restrict__ Cout)
{
    __shared__ __align__(16) __half sA[3][128 * 32];
    __shared__ __align__(16) __half sB[3][128 * 32];

    const __half* A; const __half* W; float* qkv = nullptr;
    if (MODE == 1) {
        int z = blockIdx.z;
        A   = g_xh;
        W   = g_wh + (size_t)z * DMODEL * DMODEL;
        qkv = (z == 0) ? g_q : (z == 1) ? g_k : g_v;
    } else {
        A = g_aoh;
        W = g_wh + (size_t)3 * DMODEL * DMODEL;
    }

    const int tid  = threadIdx.x;
    const int lane = tid & 31;
    const int wid  = tid >> 5;
    const int wm   = (wid >> 2) * 64;     // warp row offset in tile
    const int wn   = (wid & 3) * 32;      // warp col offset in tile
    const int row0 = blockIdx.y * 128;
    const int col0 = blockIdx.x * 128;

    // cp.async source mapping: thread -> (row = tid>>1, k-half = tid&1)
    const int lrow = tid >> 1;
    const int lseg = tid & 1;
    const __half* gA = A + (size_t)(row0 + lrow) * DMODEL + lseg * 16;
    const __half* gB = W + (size_t)(col0 + lrow) * DMODEL + lseg * 16;
    const uint32_t o0 = swz(lrow, lseg * 2);
    const uint32_t o1 = swz(lrow, lseg * 2 + 1);

    uint32_t baA[3], baB[3];
#pragma unroll
    for (int s = 0; s < 3; s++) {
        baA[s] = smem_u32(&sA[s][0]);
        baB[s] = smem_u32(&sB[s][0]);
    }

    // ldmatrix lane decomposition
    const int lr = lane & 7;
    const int lg = lane >> 3;

    float c[4][4][4];
#pragma unroll
    for (int mt = 0; mt < 4; mt++)
#pragma unroll
        for (int nt = 0; nt < 4; nt++)
#pragma unroll
            for (int e = 0; e < 4; e++) c[mt][nt][e] = 0.0f;

    // pipeline prologue: tiles 0 and 1
#pragma unroll
    for (int t = 0; t < 2; t++) {
        int s = t; int kt = t * 32;
        CP16(baA[s] + o0, gA + kt);
        CP16(baA[s] + o1, gA + kt + 8);
        CP16(baB[s] + o0, gB + kt);
        CP16(baB[s] + o1, gB + kt + 8);
        CP_COMMIT();
    }

    for (int i = 0; i < 32; i++) {
        if (i < 31) { CP_WAIT(1); } else { CP_WAIT(0); }
        __syncthreads();                  // tile i visible; stage (i+2)%3 free

        if (i + 2 < 32) {
            int t = i + 2, s = t % 3, kt = t * 32;
            CP16(baA[s] + o0, gA + kt);
            CP16(baA[s] + o1, gA + kt + 8);
            CP16(baB[s] + o0, gB + kt);
            CP16(baB[s] + o1, gB + kt + 8);
            CP_COMMIT();
        }

        const int s = i % 3;
        const uint32_t bA = baA[s], bB = baB[s];

#pragma unroll
        for (int kc = 0; kc < 2; kc++) {
            uint32_t afr[4][4];
            uint32_t bfr[8];
#pragma unroll
            for (int mt = 0; mt < 4; mt++) {
                int row = wm + mt * 16 + lr + ((lg & 1) << 3);
                int ch  = kc * 2 + (lg >> 1);
                LDSM4(afr[mt], bA + swz(row, ch));
            }
            // B fragments: NON-trans ldmatrix. matrices per x4:
            //   lg=0:(n0-7,k-lo) lg=1:(n0-7,k-hi) lg=2:(n8-15,k-lo) lg=3:(n8-15,k-hi)
            // -> bfr[nt*2] = k-lo reg, bfr[nt*2+1] = k-hi reg for n-tile nt
#pragma unroll
            for (int p = 0; p < 2; p++) {
                int row = wn + p * 16 + lr + ((lg >> 1) << 3);
                int ch  = kc * 2 + (lg & 1);
                LDSM4(&bfr[p * 4], bB + swz(row, ch));
            }
#pragma unroll
            for (int mt = 0; mt < 4; mt++)
#pragma unroll
                for (int nt = 0; nt < 4; nt++)
                    MMA16816(c[mt][nt], afr[mt], &bfr[nt * 2]);
        }
    }

    // epilogue: per (mt,nt): rows r, r+8; cols e, e+1 (float2 stores)
#pragma unroll
    for (int mt = 0; mt < 4; mt++) {
#pragma unroll
        for (int nt = 0; nt < 4; nt++) {
            int r  = row0 + wm + mt * 16 + (lane >> 2);
            int e  = col0 + wn + nt * 8 + (lane & 3) * 2;
#pragma unroll
            for (int half_ = 0; half_ < 2; half_++) {
                int m = r + half_ * 8;
                float2 v;
                v.x = c[mt][nt][half_ * 2 + 0];
                v.y = c[mt][nt][half_ * 2 + 1];
                if (MODE == 1) {
                    int b_ = m >> 10, n_ = m & 1023;
                    int h_ = e >> 6,  d_ = e & 63;
                    *(float2*)(qkv + (((size_t)b_ * NH + h_) * SEQ + n_) * HD + d_) = v;
                } else {
                    *(float2*)(Cout + (size_t)m * DMODEL + e) = v;
                }
            }
        }
    }
}

// ============================================================
// 2D axial RoPE + RMSNorm, in place on g_q / g_k. (unchanged)
// ============================================================
__global__ __launch_bounds__(128) void rope_norm_kernel(
    const int* __restrict__ ridx,
    const float* __restrict__ qw,
    const float* __restrict__ kw)
{
    int warp = threadIdx.x >> 5;
    int lane = threadIdx.x & 31;
    size_t row = (size_t)blockIdx.x * 4 + warp;
    float* base = ((blockIdx.y == 0) ? g_q : g_k) + row * HD;
    const float* w = (blockIdx.y == 0) ? qw : kw;

    int n   = (int)(row & (SEQ - 1));
    int idx = ridx[n];

    float a = base[lane*2 + 0];
    float b = base[lane*2 + 1];

    if (idx >= 0) {
        float pos = (lane < 16) ? (float)(idx >> 5) : (float)(idx & 31);
        int   jj  = lane & 15;
        float invf = expf(-0.5756462732485115f * (float)jj);
        float ang  = pos * invf;
        float s, c;
        sincosf(ang, &s, &c);
        float na = a * c - b * s;
        float nb = b * c + a * s;
        a = na; b = nb;
    }

    float ss = a * a + b * b;
#pragma unroll
    for (int m = 16; m >= 1; m >>= 1)
        ss += __shfl_xor_sync(0xffffffffu, ss, m);
    float rinv = rsqrtf(ss * (1.0f / 64.0f) + 1e-6f);

    base[lane*2 + 0] = a * rinv * w[lane*2 + 0];
    base[lane*2 + 1] = b * rinv * w[lane*2 + 1];
}

// ============================================================
// Attention (fp32 SIMT), output written as fp16 into g_aoh.
// ============================================================
__global__ __launch_bounds__(256) void attn_kernel()
{
    __shared__ float Qs[64][64];
    __shared__ float KPs[64][64];
    __shared__ float Vs[64][64];

    const int tid = threadIdx.x;
    const int tx = tid & 15;
    const int ty = tid >> 4;
    const int bh = blockIdx.y;
    const int qb = blockIdx.x;

    const float* qbase = g_q + ((size_t)bh * SEQ + qb * 64) * HD;
    const float* kbase = g_k + (size_t)bh * SEQ * HD;
    const float* vbase = g_v + (size_t)bh * SEQ * HD;

    {
        int r = tid >> 2;
        int c = (tid & 3) << 2;
        const float* src = qbase + (size_t)r * HD + c;
#pragma unroll
        for (int rep = 0; rep < 4; rep++) {
            float4 qv = *(const float4*)(src + rep * 16);
            int cc = c + rep * 16;
            Qs[cc+0][r] = qv.x; Qs[cc+1][r] = qv.y; Qs[cc+2][r] = qv.z; Qs[cc+3][r] = qv.w;
        }
    }

    float o[4][4];
    float lsum[4];
#pragma unroll
    for (int i = 0; i < 4; i++) {
        lsum[i] = 0.0f;
#pragma unroll
        for (int j = 0; j < 4; j++) o[i][j] = 0.0f;
    }

    const float scale = 0.125f;
    const float icap  = 1.0f / 50.0f;

    for (int t = 0; t < 16; t++) {
        __syncthreads();
        {
            int r = tid >> 2;
            int c = (tid & 3) << 2;
            const float* ksrc = kbase + ((size_t)t * 64 + r) * HD + c;
            const float* vsrc = vbase + ((size_t)t * 64 + r) * HD + c;
#pragma unroll
            for (int rep = 0; rep < 4; rep++) {
                float4 kv = *(const float4*)(ksrc + rep * 16);
                int cc = c + rep * 16;
                KPs[cc+0][r] = kv.x; KPs[cc+1][r] = kv.y; KPs[cc+2][r] = kv.z; KPs[cc+3][r] = kv.w;
                float4 vv = *(const float4*)(vsrc + rep * 16);
                *(float4*)&Vs[r][cc] = vv;
            }
        }
        __syncthreads();

        float s[4][4];
#pragma unroll
        for (int i = 0; i < 4; i++)
#pragma unroll
            for (int j = 0; j < 4; j++) s[i][j] = 0.0f;

#pragma unroll 16
        for (int d = 0; d < 64; d++) {
            float a[4], b[4];
            *(float4*)a = *(const float4*)&Qs[d][ty*4];
            *(float4*)b = *(const float4*)&KPs[d][tx*4];
#pragma unroll
            for (int i = 0; i < 4; i++)
#pragma unroll
                for (int j = 0; j < 4; j++)
                    s[i][j] += a[i] * b[j];
        }

#pragma unroll
        for (int i = 0; i < 4; i++) {
#pragma unroll
            for (int j = 0; j < 4; j++) {
                float sv = s[i][j] * scale;
                float u  = sv * icap;
                float u2 = u * u;
                float capped = sv * (1.0f + u2 * (-0.333333333f +
                               u2 * (0.1333333333f + u2 * (-0.05396825397f))));
                float p = __expf(capped);
                lsum[i] += p;
                s[i][j] = p;
            }
        }

        __syncthreads();
#pragma unroll
        for (int i = 0; i < 4; i++)
#pragma unroll
            for (int j = 0; j < 4; j++)
                KPs[tx*4 + j][ty*4 + i] = s[i][j];
        __syncthreads();

#pragma unroll 16
        for (int kk = 0; kk < 64; kk++) {
            float p[4], v[4];
            *(float4*)p = *(const float4*)&KPs[kk][ty*4];
            *(float4*)v = *(const float4*)&Vs[kk][tx*4];
#pragma unroll
            for (int i = 0; i < 4; i++)
#pragma unroll
                for (int j = 0; j < 4; j++)
                    o[i][j] += p[i] * v[j];
        }
    }

    const int b_ = bh >> 4;
    const int h_ = bh & 15;
#pragma unroll
    for (int i = 0; i < 4; i++) {
        float l = lsum[i];
        l += __shfl_xor_sync(0xffffffffu, l, 8);
        l += __shfl_xor_sync(0xffffffffu, l, 4);
        l += __shfl_xor_sync(0xffffffffu, l, 2);
        l += __shfl_xor_sync(0xffffffffu, l, 1);
        float inv = 1.0f / l;
        int n = qb * 64 + ty * 4 + i;
        __half* dst = g_aoh + ((size_t)b_ * SEQ + n) * DMODEL + h_ * HD + tx * 4;
        __half2 p0 = __floats2half2_rn(o[i][0] * inv, o[i][1] * inv);
        __half2 p1 = __floats2half2_rn(o[i][2] * inv, o[i][3] * inv);
        *(__half2*)(dst + 0) = p0;
        *(__half2*)(dst + 2) = p1;
    }
}

// ============================================================
// launcher
// ============================================================
extern "C" void kernel_launch(void* const* d_in, const int* in_sizes, int n_in,
                              void* d_out, int out_size)
{
    const float* x   = (const float*)d_in[0];
    const float* Wq  = (const float*)d_in[1];
    const float* Wk  = (const float*)d_in[2];
    const float* Wv  = (const float*)d_in[3];
    const float* Wo  = (const float*)d_in[4];
    const float* qw  = (const float*)d_in[5];
    const float* kw  = (const float*)d_in[6];
    const int*   ri  = (const int*)  d_in[7];
    float* out = (float*)d_out;

    // 0) fp32 -> fp16 for x and all weights
    convert_kernel<<<8192, 256>>>(x, Wq, Wk, Wv, Wo);

    // 1) QKV projections -> g_q/g_k/g_v in (B,H,N,hd)  [fp16 mma.sync]
    gemm_hmma_kernel<1><<<dim3(DMODEL/128, (BATCH*SEQ)/128, 3), 256>>>(nullptr);

    // 2) RoPE + RMSNorm in place on q and k (fp32)
    rope_norm_kernel<<<dim3((BHTOT*SEQ)/4, 2), 128>>>(ri, qw, kw);

    // 3) attention -> g_aoh (fp16) in (B,N,D)
    attn_kernel<<<dim3(SEQ/64, BHTOT), 256>>>();

    // 4) output projection -> d_out (fp32)  [fp16 mma.sync]
    gemm_hmma_kernel<0><<<dim3(DMODEL/128, (BATCH*SEQ)/128, 1), 256>>>(out);
}

// round 16
// speedup vs baseline: 4.8045x; 2.6096x over previous
#include <cuda_runtime.h>
#include <cuda_fp16.h>
#include <math.h>
#include <stdint.h>

#define BATCH   4
#define SEQ     1024
#define DMODEL  1024
#define NH      16
#define HD      64
#define BHTOT   (BATCH*NH)

// ---- scratch (device globals; no allocation allowed) ----
__device__ float  g_q  [BATCH*NH*SEQ*HD];     // fp32 q (pre-rope)
__device__ float  g_k  [BATCH*NH*SEQ*HD];     // fp32 k (pre-rope)
__device__ __half g_qh [BATCH*NH*SEQ*HD];     // fp16 q (post rope+norm)
__device__ __half g_kh [BATCH*NH*SEQ*HD];     // fp16 k
__device__ __half g_vh [BATCH*NH*SEQ*HD];     // fp16 v (written by gemm)
__device__ __half g_xh [BATCH*SEQ*DMODEL];
__device__ __half g_wh [4*DMODEL*DMODEL];     // Wq,Wk,Wv,Wo in fp16
__device__ __half g_aoh[BATCH*SEQ*DMODEL];    // attention output (fp16)

// ============================================================
// PTX helpers (baseline sm_80+ features only)
// ============================================================
__device__ __forceinline__ uint32_t smem_u32(const void* p) {
    uint32_t a;
    asm("{ .reg .u64 t; cvta.to.shared.u64 t, %1; cvt.u32.u64 %0, t; }"
        : "=r"(a) : "l"(p));
    return a;
}

__device__ __forceinline__ uint32_t h2_bits(__half2 h) {
    return *reinterpret_cast<uint32_t*>(&h);
}

#define CP16(dst, src) \
    asm volatile("cp.async.cg.shared.global [%0], [%1], 16;" \
        :: "r"(dst), "l"(src) : "memory")
#define CP_COMMIT() asm volatile("cp.async.commit_group;" ::: "memory")
#define CP_WAIT(n)  asm volatile("cp.async.wait_group %0;" :: "n"(n) : "memory")

#define LDSM4(r, addr) \
    asm volatile("ldmatrix.sync.aligned.m8n8.x4.shared.b16 {%0,%1,%2,%3}, [%4];" \
        : "=r"((r)[0]), "=r"((r)[1]), "=r"((r)[2]), "=r"((r)[3]) : "r"(addr))

#define LDSM4T(r, addr) \
    asm volatile("ldmatrix.sync.aligned.m8n8.x4.trans.shared.b16 {%0,%1,%2,%3}, [%4];" \
        : "=r"((r)[0]), "=r"((r)[1]), "=r"((r)[2]), "=r"((r)[3]) : "r"(addr))

#define MMA16816(c, a, b) \
    asm volatile("mma.sync.aligned.m16n8k16.row.col.f32.f16.f16.f32 " \
        "{%0,%1,%2,%3}, {%4,%5,%6,%7}, {%8,%9}, {%0,%1,%2,%3};" \
        : "+f"((c)[0]), "+f"((c)[1]), "+f"((c)[2]), "+f"((c)[3]) \
        : "r"((a)[0]), "r"((a)[1]), "r"((a)[2]), "r"((a)[3]), \
          "r"((b)[0]), "r"((b)[1]))

// 64B-row swizzle (gemm tiles: 32 fp16/row)
__device__ __forceinline__ uint32_t swz(int row, int chunk) {
    return (uint32_t)(row * 64 + ((chunk ^ ((row >> 1) & 3)) << 4));
}
// 128B-row swizzle (attn tiles: 64 fp16/row), byte offset
__device__ __forceinline__ uint32_t swz128(int row, int chunk) {
    return (uint32_t)(row * 128 + ((chunk ^ (row & 7)) << 4));
}

// softcap(50) + exp, entirely on FMA/ALU pipes (no MUFU).
// |c*0.125| <= ~8 -> capped in [-8,8], y in [-11.6,11.6].
__device__ __forceinline__ float softcap_exp(float c) {
    float sv = c * 0.125f;
    float u2 = sv * sv * 4.0e-4f;                 // (sv/50)^2
    float capped = sv * (1.0f + u2 * (-0.3333333333f + u2 * 0.1333333333f));
    float y = capped * 1.4426950408889634f;       // log2(e)
    float z = y + 12582912.0f;                    // 1.5*2^23: round-to-nearest-int
    int   ib = __float_as_int(z);
    float f = y - (z - 12582912.0f);              // f in [-0.5, 0.5]
    float p = 1.0f + f * (0.69314718f + f * (0.24022651f +
              f * (0.05550411f + f * 0.00961804f)));   // 2^f
    return p * __int_as_float((ib << 23) + 0x3F800000); // * 2^i
}

// ============================================================
// fp32 -> fp16 conversion of x and the four weight matrices.
// ============================================================
__global__ __launch_bounds__(256) void convert_kernel(
    const float* __restrict__ x,
    const float* __restrict__ wq, const float* __restrict__ wk,
    const float* __restrict__ wv, const float* __restrict__ wo)
{
    int v = blockIdx.x * 256 + threadIdx.x;            // 0 .. 2M-1
    const int XV = (BATCH * SEQ * DMODEL) / 4;         // 1M float4
    const int WV = (DMODEL * DMODEL) / 4;              // 256K float4
    const float* src;
    __half* dst;
    if (v < XV) {
        src = x + (size_t)v * 4;
        dst = g_xh + (size_t)v * 4;
    } else {
        int w  = v - XV;
        int wi = w / WV;
        int off = w - wi * WV;
        const float* ws = (wi == 0) ? wq : (wi == 1) ? wk : (wi == 2) ? wv : wo;
        src = ws + (size_t)off * 4;
        dst = g_wh + (size_t)wi * DMODEL * DMODEL + (size_t)off * 4;
    }
    float4 f = *(const float4*)src;
    __half2 h0 = __floats2half2_rn(f.x, f.y);
    __half2 h1 = __floats2half2_rn(f.z, f.w);
    *(__half2*)(dst)     = h0;
    *(__half2*)(dst + 2) = h1;
}

// ============================================================
// fp16 mma.sync GEMM (validated R13).  MODE 1: z in {0,1,2} ->
// q(fp32), k(fp32), v(fp16 direct). MODE 0: aoh @ Wo -> Cout.
// ============================================================
template<int MODE>
__global__ __launch_bounds__(256) void gemm_hmma_kernel(float* __restrict__ Cout)
{
    __shared__ __align__(16) __half sA[3][128 * 32];
    __shared__ __align__(16) __half sB[3][128 * 32];

    const __half* A; const __half* W; float* qkv = nullptr;
    if (MODE == 1) {
        int z = blockIdx.z;
        A   = g_xh;
        W   = g_wh + (size_t)z * DMODEL * DMODEL;
        qkv = (z == 0) ? g_q : g_k;      // z==2 handled at epilogue (fp16)
    } else {
        A = g_aoh;
        W = g_wh + (size_t)3 * DMODEL * DMODEL;
    }

    const int tid  = threadIdx.x;
    const int lane = tid & 31;
    const int wid  = tid >> 5;
    const int wm   = (wid >> 2) * 64;
    const int wn   = (wid & 3) * 32;
    const int row0 = blockIdx.y * 128;
    const int col0 = blockIdx.x * 128;

    const int lrow = tid >> 1;
    const int lseg = tid & 1;
    const __half* gA = A + (size_t)(row0 + lrow) * DMODEL + lseg * 16;
    const __half* gB = W + (size_t)(col0 + lrow) * DMODEL + lseg * 16;
    const uint32_t o0 = swz(lrow, lseg * 2);
    const uint32_t o1 = swz(lrow, lseg * 2 + 1);

    uint32_t baA[3], baB[3];
#pragma unroll
    for (int s = 0; s < 3; s++) {
        baA[s] = smem_u32(&sA[s][0]);
        baB[s] = smem_u32(&sB[s][0]);
    }

    const int lr = lane & 7;
    const int lg = lane >> 3;

    float c[4][4][4];
#pragma unroll
    for (int mt = 0; mt < 4; mt++)
#pragma unroll
        for (int nt = 0; nt < 4; nt++)
#pragma unroll
            for (int e = 0; e < 4; e++) c[mt][nt][e] = 0.0f;

#pragma unroll
    for (int t = 0; t < 2; t++) {
        int s = t; int kt = t * 32;
        CP16(baA[s] + o0, gA + kt);
        CP16(baA[s] + o1, gA + kt + 8);
        CP16(baB[s] + o0, gB + kt);
        CP16(baB[s] + o1, gB + kt + 8);
        CP_COMMIT();
    }

    for (int i = 0; i < 32; i++) {
        if (i < 31) { CP_WAIT(1); } else { CP_WAIT(0); }
        __syncthreads();

        if (i + 2 < 32) {
            int t = i + 2, s = t % 3, kt = t * 32;
            CP16(baA[s] + o0, gA + kt);
            CP16(baA[s] + o1, gA + kt + 8);
            CP16(baB[s] + o0, gB + kt);
            CP16(baB[s] + o1, gB + kt + 8);
            CP_COMMIT();
        }

        const int s = i % 3;
        const uint32_t bA = baA[s], bB = baB[s];

#pragma unroll
        for (int kc = 0; kc < 2; kc++) {
            uint32_t afr[4][4];
            uint32_t bfr[8];
#pragma unroll
            for (int mt = 0; mt < 4; mt++) {
                int row = wm + mt * 16 + lr + ((lg & 1) << 3);
                int ch  = kc * 2 + (lg >> 1);
                LDSM4(afr[mt], bA + swz(row, ch));
            }
#pragma unroll
            for (int p = 0; p < 2; p++) {
                int row = wn + p * 16 + lr + ((lg >> 1) << 3);
                int ch  = kc * 2 + (lg & 1);
                LDSM4(&bfr[p * 4], bB + swz(row, ch));
            }
#pragma unroll
            for (int mt = 0; mt < 4; mt++)
#pragma unroll
                for (int nt = 0; nt < 4; nt++)
                    MMA16816(c[mt][nt], afr[mt], &bfr[nt * 2]);
        }
    }

#pragma unroll
    for (int mt = 0; mt < 4; mt++) {
#pragma unroll
        for (int nt = 0; nt < 4; nt++) {
            int r  = row0 + wm + mt * 16 + (lane >> 2);
            int e  = col0 + wn + nt * 8 + (lane & 3) * 2;
#pragma unroll
            for (int half_ = 0; half_ < 2; half_++) {
                int m = r + half_ * 8;
                float2 v;
                v.x = c[mt][nt][half_ * 2 + 0];
                v.y = c[mt][nt][half_ * 2 + 1];
                if (MODE == 1) {
                    int b_ = m >> 10, n_ = m & 1023;
                    int h_ = e >> 6,  d_ = e & 63;
                    size_t idx = (((size_t)b_ * NH + h_) * SEQ + n_) * HD + d_;
                    if (blockIdx.z == 2)
                        *(__half2*)(g_vh + idx) = __floats2half2_rn(v.x, v.y);
                    else
                        *(float2*)(qkv + idx) = v;
                } else {
                    *(float2*)(Cout + (size_t)m * DMODEL + e) = v;
                }
            }
        }
    }
}

// ============================================================
// 2D axial RoPE + RMSNorm: read fp32 g_q/g_k, write fp16 g_qh/g_kh
// ============================================================
__global__ __launch_bounds__(128) void rope_norm_kernel(
    const int* __restrict__ ridx,
    const float* __restrict__ qw,
    const float* __restrict__ kw)
{
    int warp = threadIdx.x >> 5;
    int lane = threadIdx.x & 31;
    size_t row = (size_t)blockIdx.x * 4 + warp;
    const float* base = ((blockIdx.y == 0) ? g_q : g_k) + row * HD;
    __half*     dsth = ((blockIdx.y == 0) ? g_qh : g_kh) + row * HD;
    const float* w = (blockIdx.y == 0) ? qw : kw;

    int n   = (int)(row & (SEQ - 1));
    int idx = ridx[n];

    float a = base[lane*2 + 0];
    float b = base[lane*2 + 1];

    if (idx >= 0) {
        float pos = (lane < 16) ? (float)(idx >> 5) : (float)(idx & 31);
        int   jj  = lane & 15;
        float invf = expf(-0.5756462732485115f * (float)jj);
        float ang  = pos * invf;
        float s, c;
        sincosf(ang, &s, &c);
        float na = a * c - b * s;
        float nb = b * c + a * s;
        a = na; b = nb;
    }

    float ss = a * a + b * b;
#pragma unroll
    for (int m = 16; m >= 1; m >>= 1)
        ss += __shfl_xor_sync(0xffffffffu, ss, m);
    float rinv = rsqrtf(ss * (1.0f / 64.0f) + 1e-6f);

    *(__half2*)(dsth + lane*2) =
        __floats2half2_rn(a * rinv * w[lane*2 + 0], b * rinv * w[lane*2 + 1]);
}

// ============================================================
// HMMA flash attention. CTA = 128 queries of one (b,h).
// 8 warps (16 q-rows each), KV tiles of 64, double-buffered.
// S c-frag layout == P a-frag layout (no shuffles).
// Softcap bounds scores -> one-pass sum, no max tracking.
// ============================================================
__global__ __launch_bounds__(256) void attn_hmma_kernel()
{
    __shared__ __align__(16) __half sQ[128 * 64];      // 16KB
    __shared__ __align__(16) __half sK[2][64 * 64];    // 2x8KB
    __shared__ __align__(16) __half sV[2][64 * 64];    // 2x8KB

    const int tid  = threadIdx.x;
    const int lane = tid & 31;
    const int wid  = tid >> 5;
    const int lr   = lane & 7;
    const int lg   = lane >> 3;
    const int bh   = blockIdx.y;
    const int qb   = blockIdx.x;

    const __half* qbase = g_qh + ((size_t)bh * SEQ + qb * 128) * HD;
    const __half* kbase = g_kh + (size_t)bh * SEQ * HD;
    const __half* vbase = g_vh + (size_t)bh * SEQ * HD;

    const uint32_t bQ = smem_u32(sQ);
    uint32_t bK[2] = { smem_u32(&sK[0][0]), smem_u32(&sK[1][0]) };
    uint32_t bV[2] = { smem_u32(&sV[0][0]), smem_u32(&sV[1][0]) };

    // ---- prologue: load Q (whole) + K0,V0 via cp.async ----
    {
        int qr = tid >> 1;                 // 0..127
        int qc0 = (tid & 1) * 4;
#pragma unroll
        for (int j = 0; j < 4; j++) {
            int cgl = qc0 + j;
            CP16(bQ + swz128(qr, cgl), qbase + (size_t)qr * HD + cgl * 8);
        }
        int r = tid >> 2;                  // 0..63
        int c0 = (tid & 3) * 2;
#pragma unroll
        for (int j = 0; j < 2; j++) {
            int cgl = c0 + j;
            CP16(bK[0] + swz128(r, cgl), kbase + (size_t)r * HD + cgl * 8);
            CP16(bV[0] + swz128(r, cgl), vbase + (size_t)r * HD + cgl * 8);
        }
        CP_COMMIT();
    }
    CP_WAIT(0);
    __syncthreads();

    // ---- Q fragments: register-resident for all 16 tiles ----
    const int wq0 = wid * 16;
    uint32_t qf[4][4];
#pragma unroll
    for (int kc = 0; kc < 4; kc++)
        LDSM4(qf[kc], bQ + swz128(wq0 + lr + ((lg & 1) << 3), kc * 2 + (lg >> 1)));

    float o[8][4];
#pragma unroll
    for (int nt = 0; nt < 8; nt++)
#pragma unroll
        for (int e = 0; e < 4; e++) o[nt][e] = 0.0f;
    float lsum0 = 0.0f, lsum1 = 0.0f;

    for (int t = 0; t < 16; t++) {
        CP_WAIT(0);
        __syncthreads();      // tile t visible; all reads of tile t-1 done

        if (t + 1 < 16) {     // prefetch tile t+1 into the other buffer
            int r = tid >> 2;
            int c0 = (tid & 3) * 2;
            const __half* ks = kbase + ((size_t)(t + 1) * 64 + r) * HD;
            const __half* vs = vbase + ((size_t)(t + 1) * 64 + r) * HD;
            uint32_t kb = bK[(t + 1) & 1], vb = bV[(t + 1) & 1];
#pragma unroll
            for (int j = 0; j < 2; j++) {
                int cgl = c0 + j;
                CP16(kb + swz128(r, cgl), ks + cgl * 8);
                CP16(vb + swz128(r, cgl), vs + cgl * 8);
            }
            CP_COMMIT();
        }

        const uint32_t kb = bK[t & 1], vb = bV[t & 1];

        // ---- S = Q K^T ----
        float sc[8][4];
#pragma unroll
        for (int nt = 0; nt < 8; nt++)
#pragma unroll
            for (int e = 0; e < 4; e++) sc[nt][e] = 0.0f;

#pragma unroll
        for (int kc = 0; kc < 4; kc++) {
            uint32_t kfr[16];
#pragma unroll
            for (int p = 0; p < 4; p++)
                LDSM4(&kfr[p * 4],
                      kb + swz128(p * 16 + lr + ((lg >> 1) << 3), kc * 2 + (lg & 1)));
#pragma unroll
            for (int p = 0; p < 4; p++) {
                MMA16816(sc[2 * p + 0], qf[kc], &kfr[p * 4 + 0]);
                MMA16816(sc[2 * p + 1], qf[kc], &kfr[p * 4 + 2]);
            }
        }

        // ---- softcap + exp (FMA pipe) -> P fp16 a-frags + row sums ----
        uint32_t pf[4][4];
#pragma unroll
        for (int nt = 0; nt < 8; nt++) {
            float p0 = softcap_exp(sc[nt][0]);
            float p1 = softcap_exp(sc[nt][1]);
            float p2 = softcap_exp(sc[nt][2]);
            float p3 = softcap_exp(sc[nt][3]);
            lsum0 += p0 + p1;
            lsum1 += p2 + p3;
            pf[nt >> 1][(nt & 1) * 2 + 0] = h2_bits(__floats2half2_rn(p0, p1));
            pf[nt >> 1][(nt & 1) * 2 + 1] = h2_bits(__floats2half2_rn(p2, p3));
        }

        // ---- O += P V ----
#pragma unroll
        for (int kcp = 0; kcp < 4; kcp++) {
            uint32_t vfr[16];
#pragma unroll
            for (int p = 0; p < 4; p++)
                LDSM4T(&vfr[p * 4],
                       vb + swz128(kcp * 16 + lr + ((lg & 1) << 3), p * 2 + (lg >> 1)));
#pragma unroll
            for (int p = 0; p < 4; p++) {
                MMA16816(o[2 * p + 0], pf[kcp], &vfr[p * 4 + 0]);
                MMA16816(o[2 * p + 1], pf[kcp], &vfr[p * 4 + 2]);
            }
        }
    }

    // ---- normalize + write (fp16 into g_aoh) ----
    lsum0 += __shfl_xor_sync(0xffffffffu, lsum0, 1);
    lsum0 += __shfl_xor_sync(0xffffffffu, lsum0, 2);
    lsum1 += __shfl_xor_sync(0xffffffffu, lsum1, 1);
    lsum1 += __shfl_xor_sync(0xffffffffu, lsum1, 2);
    float inv0 = 1.0f / lsum0;
    float inv1 = 1.0f / lsum1;

    const int b_ = bh >> 4;
    const int h_ = bh & 15;
    const int r0 = qb * 128 + wq0 + (lane >> 2);
#pragma unroll
    for (int nt = 0; nt < 8; nt++) {
        int d0 = nt * 8 + (lane & 3) * 2;
        __half* dst0 = g_aoh + ((size_t)b_ * SEQ + r0) * DMODEL + h_ * HD + d0;
        __half* dst1 = g_aoh + ((size_t)b_ * SEQ + r0 + 8) * DMODEL + h_ * HD + d0;
        *(__half2*)dst0 = __floats2half2_rn(o[nt][0] * inv0, o[nt][1] * inv0);
        *(__half2*)dst1 = __floats2half2_rn(o[nt][2] * inv1, o[nt][3] * inv1);
    }
}

// ============================================================
// launcher
// ============================================================
extern "C" void kernel_launch(void* const* d_in, const int* in_sizes, int n_in,
                              void* d_out, int out_size)
{
    const float* x   = (const float*)d_in[0];
    const float* Wq  = (const float*)d_in[1];
    const float* Wk  = (const float*)d_in[2];
    const float* Wv  = (const float*)d_in[3];
    const float* Wo  = (const float*)d_in[4];
    const float* qw  = (const float*)d_in[5];
    const float* kw  = (const float*)d_in[6];
    const int*   ri  = (const int*)  d_in[7];
    float* out = (float*)d_out;

    // 0) fp32 -> fp16 for x and all weights
    convert_kernel<<<8192, 256>>>(x, Wq, Wk, Wv, Wo);

    // 1) QKV projections: q,k fp32; v fp16 direct  [fp16 mma.sync]
    gemm_hmma_kernel<1><<<dim3(DMODEL/128, (BATCH*SEQ)/128, 3), 256>>>(nullptr);

    // 2) RoPE + RMSNorm: fp32 in, fp16 out
    rope_norm_kernel<<<dim3((BHTOT*SEQ)/4, 2), 128>>>(ri, qw, kw);

    // 3) attention (HMMA, FMA-exp) -> g_aoh fp16
    attn_hmma_kernel<<<dim3(SEQ/128, BHTOT), 256>>>();

    // 4) output projection -> d_out  [fp16 mma.sync]
    gemm_hmma_kernel<0><<<dim3(DMODEL/128, (BATCH*SEQ)/128, 1), 256>>>(out);
}

// round 17
// speedup vs baseline: 5.1230x; 1.0663x over previous
#include <cuda_runtime.h>
#include <cuda_fp16.h>
#include <math.h>
#include <stdint.h>

#define BATCH   4
#define SEQ     1024
#define DMODEL  1024
#define NH      16
#define HD      64
#define BHTOT   (BATCH*NH)

// ---- scratch (device globals; no allocation allowed) ----
__device__ float  g_q  [BATCH*NH*SEQ*HD];     // fp32 q (pre-rope)
__device__ float  g_k  [BATCH*NH*SEQ*HD];     // fp32 k (pre-rope)
__device__ __half g_qh [BATCH*NH*SEQ*HD];     // fp16 q (post rope+norm)
__device__ __half g_kh [BATCH*NH*SEQ*HD];     // fp16 k
__device__ __half g_vh [BATCH*NH*SEQ*HD];     // fp16 v (written by gemm)
__device__ __half g_xh [BATCH*SEQ*DMODEL];
__device__ __half g_wh [4*DMODEL*DMODEL];     // Wq,Wk,Wv,Wo in fp16
__device__ __half g_aoh[BATCH*SEQ*DMODEL];    // attention output (fp16)

// ============================================================
// PTX helpers (baseline sm_80+ features only)
// ============================================================
__device__ __forceinline__ uint32_t smem_u32(const void* p) {
    uint32_t a;
    asm("{ .reg .u64 t; cvta.to.shared.u64 t, %1; cvt.u32.u64 %0, t; }"
        : "=r"(a) : "l"(p));
    return a;
}

__device__ __forceinline__ uint32_t h2_bits(__half2 h) {
    return *reinterpret_cast<uint32_t*>(&h);
}

#define CP16(dst, src) \
    asm volatile("cp.async.cg.shared.global [%0], [%1], 16;" \
        :: "r"(dst), "l"(src) : "memory")
#define CP_COMMIT() asm volatile("cp.async.commit_group;" ::: "memory")
#define CP_WAIT(n)  asm volatile("cp.async.wait_group %0;" :: "n"(n) : "memory")

#define LDSM4(r, addr) \
    asm volatile("ldmatrix.sync.aligned.m8n8.x4.shared.b16 {%0,%1,%2,%3}, [%4];" \
        : "=r"((r)[0]), "=r"((r)[1]), "=r"((r)[2]), "=r"((r)[3]) : "r"(addr))

#define LDSM4T(r, addr) \
    asm volatile("ldmatrix.sync.aligned.m8n8.x4.trans.shared.b16 {%0,%1,%2,%3}, [%4];" \
        : "=r"((r)[0]), "=r"((r)[1]), "=r"((r)[2]), "=r"((r)[3]) : "r"(addr))

#define MMA16816(c, a, b) \
    asm volatile("mma.sync.aligned.m16n8k16.row.col.f32.f16.f16.f32 " \
        "{%0,%1,%2,%3}, {%4,%5,%6,%7}, {%8,%9}, {%0,%1,%2,%3};" \
        : "+f"((c)[0]), "+f"((c)[1]), "+f"((c)[2]), "+f"((c)[3]) \
        : "r"((a)[0]), "r"((a)[1]), "r"((a)[2]), "r"((a)[3]), \
          "r"((b)[0]), "r"((b)[1]))

// 64B-row swizzle (gemm tiles: 32 fp16/row)
__device__ __forceinline__ uint32_t swz(int row, int chunk) {
    return (uint32_t)(row * 64 + ((chunk ^ ((row >> 1) & 3)) << 4));
}
// 128B-row swizzle (attn tiles: 64 fp16/row), byte offset
__device__ __forceinline__ uint32_t swz128(int row, int chunk) {
    return (uint32_t)(row * 128 + ((chunk ^ (row & 7)) << 4));
}

// softcap(50) + exp, entirely on FMA/ALU pipes (no MUFU).
__device__ __forceinline__ float softcap_exp(float c) {
    float sv = c * 0.125f;
    float u2 = sv * sv * 4.0e-4f;                 // (sv/50)^2
    float capped = sv * (1.0f + u2 * (-0.3333333333f + u2 * 0.1333333333f));
    float y = capped * 1.4426950408889634f;       // log2(e)
    float z = y + 12582912.0f;                    // 1.5*2^23: round-to-nearest-int
    int   ib = __float_as_int(z);
    float f = y - (z - 12582912.0f);              // f in [-0.5, 0.5]
    float p = 1.0f + f * (0.69314718f + f * (0.24022651f +
              f * (0.05550411f + f * 0.00961804f)));   // 2^f
    return p * __int_as_float((ib << 23) + 0x3F800000); // * 2^i
}

// ============================================================
// fp32 -> fp16 conversion of x and the four weight matrices.
// ============================================================
__global__ __launch_bounds__(256) void convert_kernel(
    const float* __restrict__ x,
    const float* __restrict__ wq, const float* __restrict__ wk,
    const float* __restrict__ wv, const float* __restrict__ wo)
{
    int v = blockIdx.x * 256 + threadIdx.x;            // 0 .. 2M-1
    const int XV = (BATCH * SEQ * DMODEL) / 4;         // 1M float4
    const int WV = (DMODEL * DMODEL) / 4;              // 256K float4
    const float* src;
    __half* dst;
    if (v < XV) {
        src = x + (size_t)v * 4;
        dst = g_xh + (size_t)v * 4;
    } else {
        int w  = v - XV;
        int wi = w / WV;
        int off = w - wi * WV;
        const float* ws = (wi == 0) ? wq : (wi == 1) ? wk : (wi == 2) ? wv : wo;
        src = ws + (size_t)off * 4;
        dst = g_wh + (size_t)wi * DMODEL * DMODEL + (size_t)off * 4;
    }
    float4 f = *(const float4*)src;
    __half2 h0 = __floats2half2_rn(f.x, f.y);
    __half2 h1 = __floats2half2_rn(f.z, f.w);
    *(__half2*)(dst)     = h0;
    *(__half2*)(dst + 2) = h1;
}

// ============================================================
// fp16 mma.sync GEMM (validated R13).  MODE 1: z in {0,1,2} ->
// q(fp32), k(fp32), v(fp16 direct). MODE 0: aoh @ Wo -> Cout.
// ============================================================
template<int MODE>
__global__ __launch_bounds__(256) void gemm_hmma_kernel(float* __restrict__ Cout)
{
    __shared__ __align__(16) __half sA[3][128 * 32];
    __shared__ __align__(16) __half sB[3][128 * 32];

    const __half* A; const __half* W; float* qkv = nullptr;
    if (MODE == 1) {
        int z = blockIdx.z;
        A   = g_xh;
        W   = g_wh + (size_t)z * DMODEL * DMODEL;
        qkv = (z == 0) ? g_q : g_k;      // z==2 handled at epilogue (fp16)
    } else {
        A = g_aoh;
        W = g_wh + (size_t)3 * DMODEL * DMODEL;
    }

    const int tid  = threadIdx.x;
    const int lane = tid & 31;
    const int wid  = tid >> 5;
    const int wm   = (wid >> 2) * 64;
    const int wn   = (wid & 3) * 32;
    const int row0 = blockIdx.y * 128;
    const int col0 = blockIdx.x * 128;

    const int lrow = tid >> 1;
    const int lseg = tid & 1;
    const __half* gA = A + (size_t)(row0 + lrow) * DMODEL + lseg * 16;
    const __half* gB = W + (size_t)(col0 + lrow) * DMODEL + lseg * 16;
    const uint32_t o0 = swz(lrow, lseg * 2);
    const uint32_t o1 = swz(lrow, lseg * 2 + 1);

    uint32_t baA[3], baB[3];
#pragma unroll
    for (int s = 0; s < 3; s++) {
        baA[s] = smem_u32(&sA[s][0]);
        baB[s] = smem_u32(&sB[s][0]);
    }

    const int lr = lane & 7;
    const int lg = lane >> 3;

    float c[4][4][4];
#pragma unroll
    for (int mt = 0; mt < 4; mt++)
#pragma unroll
        for (int nt = 0; nt < 4; nt++)
#pragma unroll
            for (int e = 0; e < 4; e++) c[mt][nt][e] = 0.0f;

#pragma unroll
    for (int t = 0; t < 2; t++) {
        int s = t; int kt = t * 32;
        CP16(baA[s] + o0, gA + kt);
        CP16(baA[s] + o1, gA + kt + 8);
        CP16(baB[s] + o0, gB + kt);
        CP16(baB[s] + o1, gB + kt + 8);
        CP_COMMIT();
    }

    for (int i = 0; i < 32; i++) {
        if (i < 31) { CP_WAIT(1); } else { CP_WAIT(0); }
        __syncthreads();

        if (i + 2 < 32) {
            int t = i + 2, s = t % 3, kt = t * 32;
            CP16(baA[s] + o0, gA + kt);
            CP16(baA[s] + o1, gA + kt + 8);
            CP16(baB[s] + o0, gB + kt);
            CP16(baB[s] + o1, gB + kt + 8);
            CP_COMMIT();
        }

        const int s = i % 3;
        const uint32_t bA = baA[s], bB = baB[s];

#pragma unroll
        for (int kc = 0; kc < 2; kc++) {
            uint32_t afr[4][4];
            uint32_t bfr[8];
#pragma unroll
            for (int mt = 0; mt < 4; mt++) {
                int row = wm + mt * 16 + lr + ((lg & 1) << 3);
                int ch  = kc * 2 + (lg >> 1);
                LDSM4(afr[mt], bA + swz(row, ch));
            }
#pragma unroll
            for (int p = 0; p < 2; p++) {
                int row = wn + p * 16 + lr + ((lg >> 1) << 3);
                int ch  = kc * 2 + (lg & 1);
                LDSM4(&bfr[p * 4], bB + swz(row, ch));
            }
#pragma unroll
            for (int mt = 0; mt < 4; mt++)
#pragma unroll
                for (int nt = 0; nt < 4; nt++)
                    MMA16816(c[mt][nt], afr[mt], &bfr[nt * 2]);
        }
    }

#pragma unroll
    for (int mt = 0; mt < 4; mt++) {
#pragma unroll
        for (int nt = 0; nt < 4; nt++) {
            int r  = row0 + wm + mt * 16 + (lane >> 2);
            int e  = col0 + wn + nt * 8 + (lane & 3) * 2;
#pragma unroll
            for (int half_ = 0; half_ < 2; half_++) {
                int m = r + half_ * 8;
                float2 v;
                v.x = c[mt][nt][half_ * 2 + 0];
                v.y = c[mt][nt][half_ * 2 + 1];
                if (MODE == 1) {
                    int b_ = m >> 10, n_ = m & 1023;
                    int h_ = e >> 6,  d_ = e & 63;
                    size_t idx = (((size_t)b_ * NH + h_) * SEQ + n_) * HD + d_;
                    if (blockIdx.z == 2)
                        *(__half2*)(g_vh + idx) = __floats2half2_rn(v.x, v.y);
                    else
                        *(float2*)(qkv + idx) = v;
                } else {
                    *(float2*)(Cout + (size_t)m * DMODEL + e) = v;
                }
            }
        }
    }
}

// ============================================================
// 2D axial RoPE + RMSNorm: read fp32 g_q/g_k, write fp16 g_qh/g_kh
// ============================================================
__global__ __launch_bounds__(128) void rope_norm_kernel(
    const int* __restrict__ ridx,
    const float* __restrict__ qw,
    const float* __restrict__ kw)
{
    int warp = threadIdx.x >> 5;
    int lane = threadIdx.x & 31;
    size_t row = (size_t)blockIdx.x * 4 + warp;
    const float* base = ((blockIdx.y == 0) ? g_q : g_k) + row * HD;
    __half*     dsth = ((blockIdx.y == 0) ? g_qh : g_kh) + row * HD;
    const float* w = (blockIdx.y == 0) ? qw : kw;

    int n   = (int)(row & (SEQ - 1));
    int idx = ridx[n];

    float a = base[lane*2 + 0];
    float b = base[lane*2 + 1];

    if (idx >= 0) {
        float pos = (lane < 16) ? (float)(idx >> 5) : (float)(idx & 31);
        int   jj  = lane & 15;
        float invf = expf(-0.5756462732485115f * (float)jj);
        float ang  = pos * invf;
        float s, c;
        sincosf(ang, &s, &c);
        float na = a * c - b * s;
        float nb = b * c + a * s;
        a = na; b = nb;
    }

    float ss = a * a + b * b;
#pragma unroll
    for (int m = 16; m >= 1; m >>= 1)
        ss += __shfl_xor_sync(0xffffffffu, ss, m);
    float rinv = rsqrtf(ss * (1.0f / 64.0f) + 1e-6f);

    *(__half2*)(dsth + lane*2) =
        __floats2half2_rn(a * rinv * w[lane*2 + 0], b * rinv * w[lane*2 + 1]);
}

// ============================================================
// HMMA flash attention. CTA = 128 queries of one (b,h).
// 8 warps (16 q-rows each), KV tiles of 64, double-buffered.
// Register diet: K/V fragments loaded 4-reg at a time and
// consumed immediately; __launch_bounds__(256,2) -> 2 CTA/SM.
// ============================================================
__global__ __launch_bounds__(256, 2) void attn_hmma_kernel()
{
    __shared__ __align__(16) __half sQ[128 * 64];      // 16KB
    __shared__ __align__(16) __half sK[2][64 * 64];    // 2x8KB
    __shared__ __align__(16) __half sV[2][64 * 64];    // 2x8KB

    const int tid  = threadIdx.x;
    const int lane = tid & 31;
    const int wid  = tid >> 5;
    const int lr   = lane & 7;
    const int lg   = lane >> 3;
    const int bh   = blockIdx.y;
    const int qb   = blockIdx.x;

    const __half* qbase = g_qh + ((size_t)bh * SEQ + qb * 128) * HD;
    const __half* kbase = g_kh + (size_t)bh * SEQ * HD;
    const __half* vbase = g_vh + (size_t)bh * SEQ * HD;

    const uint32_t bQ = smem_u32(sQ);
    uint32_t bK[2] = { smem_u32(&sK[0][0]), smem_u32(&sK[1][0]) };
    uint32_t bV[2] = { smem_u32(&sV[0][0]), smem_u32(&sV[1][0]) };

    // ---- prologue: load Q (whole) + K0,V0 via cp.async ----
    {
        int qr = tid >> 1;                 // 0..127
        int qc0 = (tid & 1) * 4;
#pragma unroll
        for (int j = 0; j < 4; j++) {
            int cgl = qc0 + j;
            CP16(bQ + swz128(qr, cgl), qbase + (size_t)qr * HD + cgl * 8);
        }
        int r = tid >> 2;                  // 0..63
        int c0 = (tid & 3) * 2;
#pragma unroll
        for (int j = 0; j < 2; j++) {
            int cgl = c0 + j;
            CP16(bK[0] + swz128(r, cgl), kbase + (size_t)r * HD + cgl * 8);
            CP16(bV[0] + swz128(r, cgl), vbase + (size_t)r * HD + cgl * 8);
        }
        CP_COMMIT();
    }
    CP_WAIT(0);
    __syncthreads();

    // ---- Q fragments: register-resident for all 16 tiles ----
    const int wq0 = wid * 16;
    uint32_t qf[4][4];
#pragma unroll
    for (int kc = 0; kc < 4; kc++)
        LDSM4(qf[kc], bQ + swz128(wq0 + lr + ((lg & 1) << 3), kc * 2 + (lg >> 1)));

    float o[8][4];
#pragma unroll
    for (int nt = 0; nt < 8; nt++)
#pragma unroll
        for (int e = 0; e < 4; e++) o[nt][e] = 0.0f;
    float lsum0 = 0.0f, lsum1 = 0.0f;

    for (int t = 0; t < 16; t++) {
        CP_WAIT(0);
        __syncthreads();      // tile t visible; all reads of tile t-1 done

        if (t + 1 < 16) {     // prefetch tile t+1 into the other buffer
            int r = tid >> 2;
            int c0 = (tid & 3) * 2;
            const __half* ks = kbase + ((size_t)(t + 1) * 64 + r) * HD;
            const __half* vs = vbase + ((size_t)(t + 1) * 64 + r) * HD;
            uint32_t kb = bK[(t + 1) & 1], vb = bV[(t + 1) & 1];
#pragma unroll
            for (int j = 0; j < 2; j++) {
                int cgl = c0 + j;
                CP16(kb + swz128(r, cgl), ks + cgl * 8);
                CP16(vb + swz128(r, cgl), vs + cgl * 8);
            }
            CP_COMMIT();
        }

        const uint32_t kb = bK[t & 1], vb = bV[t & 1];

        // ---- S = Q K^T (K frags streamed 4 regs at a time) ----
        float sc[8][4];
#pragma unroll
        for (int nt = 0; nt < 8; nt++)
#pragma unroll
            for (int e = 0; e < 4; e++) sc[nt][e] = 0.0f;

#pragma unroll
        for (int kc = 0; kc < 4; kc++) {
#pragma unroll
            for (int p = 0; p < 4; p++) {
                uint32_t kfr[4];
                LDSM4(kfr,
                      kb + swz128(p * 16 + lr + ((lg >> 1) << 3), kc * 2 + (lg & 1)));
                MMA16816(sc[2 * p + 0], qf[kc], &kfr[0]);
                MMA16816(sc[2 * p + 1], qf[kc], &kfr[2]);
            }
        }

        // ---- softcap + exp (FMA pipe) -> P fp16 a-frags + row sums ----
        uint32_t pf[4][4];
#pragma unroll
        for (int nt = 0; nt < 8; nt++) {
            float p0 = softcap_exp(sc[nt][0]);
            float p1 = softcap_exp(sc[nt][1]);
            float p2 = softcap_exp(sc[nt][2]);
            float p3 = softcap_exp(sc[nt][3]);
            lsum0 += p0 + p1;
            lsum1 += p2 + p3;
            pf[nt >> 1][(nt & 1) * 2 + 0] = h2_bits(__floats2half2_rn(p0, p1));
            pf[nt >> 1][(nt & 1) * 2 + 1] = h2_bits(__floats2half2_rn(p2, p3));
        }

        // ---- O += P V (V frags streamed 4 regs at a time) ----
#pragma unroll
        for (int kcp = 0; kcp < 4; kcp++) {
#pragma unroll
            for (int p = 0; p < 4; p++) {
                uint32_t vfr[4];
                LDSM4T(vfr,
                       vb + swz128(kcp * 16 + lr + ((lg & 1) << 3), p * 2 + (lg >> 1)));
                MMA16816(o[2 * p + 0], pf[kcp], &vfr[0]);
                MMA16816(o[2 * p + 1], pf[kcp], &vfr[2]);
            }
        }
    }

    // ---- normalize + write (fp16 into g_aoh) ----
    lsum0 += __shfl_xor_sync(0xffffffffu, lsum0, 1);
    lsum0 += __shfl_xor_sync(0xffffffffu, lsum0, 2);
    lsum1 += __shfl_xor_sync(0xffffffffu, lsum1, 1);
    lsum1 += __shfl_xor_sync(0xffffffffu, lsum1, 2);
    float inv0 = 1.0f / lsum0;
    float inv1 = 1.0f / lsum1;

    const int b_ = bh >> 4;
    const int h_ = bh & 15;
    const int r0 = qb * 128 + wq0 + (lane >> 2);
#pragma unroll
    for (int nt = 0; nt < 8; nt++) {
        int d0 = nt * 8 + (lane & 3) * 2;
        __half* dst0 = g_aoh + ((size_t)b_ * SEQ + r0) * DMODEL + h_ * HD + d0;
        __half* dst1 = g_aoh + ((size_t)b_ * SEQ + r0 + 8) * DMODEL + h_ * HD + d0;
        *(__half2*)dst0 = __floats2half2_rn(o[nt][0] * inv0, o[nt][1] * inv0);
        *(__half2*)dst1 = __floats2half2_rn(o[nt][2] * inv1, o[nt][3] * inv1);
    }
}

// ============================================================
// launcher
// ============================================================
extern "C" void kernel_launch(void* const* d_in, const int* in_sizes, int n_in,
                              void* d_out, int out_size)
{
    const float* x   = (const float*)d_in[0];
    const float* Wq  = (const float*)d_in[1];
    const float* Wk  = (const float*)d_in[2];
    const float* Wv  = (const float*)d_in[3];
    const float* Wo  = (const float*)d_in[4];
    const float* qw  = (const float*)d_in[5];
    const float* kw  = (const float*)d_in[6];
    const int*   ri  = (const int*)  d_in[7];
    float* out = (float*)d_out;

    // 0) fp32 -> fp16 for x and all weights
    convert_kernel<<<8192, 256>>>(x, Wq, Wk, Wv, Wo);

    // 1) QKV projections: q,k fp32; v fp16 direct  [fp16 mma.sync]
    gemm_hmma_kernel<1><<<dim3(DMODEL/128, (BATCH*SEQ)/128, 3), 256>>>(nullptr);

    // 2) RoPE + RMSNorm: fp32 in, fp16 out
    rope_norm_kernel<<<dim3((BHTOT*SEQ)/4, 2), 128>>>(ri, qw, kw);

    // 3) attention (HMMA, FMA-exp, 2 CTA/SM) -> g_aoh fp16
    attn_hmma_kernel<<<dim3(SEQ/128, BHTOT), 256>>>();

    // 4) output projection -> d_out  [fp16 mma.sync]
    gemm_hmma_kernel<0><<<dim3(DMODEL/128, (BATCH*SEQ)/128, 1), 256>>>(out);
}